// round 14
// baseline (speedup 1.0000x reference)
#include <cuda_runtime.h>
#include <cuda_fp16.h>
#include <cstdint>

// ----------------------------------------------------------------------------
// Linear4bit via fp16 mma.sync (tcgen05 unavailable: PTX target sm_103).
//   out[m,o] = scale*(sum_k x_h[m,k]*wq[o,k]) - scale*zp*rowsum_h[m] + bias[o]
// R14: hoisted full-barrier wait. R12/R13 killed the "boundary alignment"
//      theory; the 12.5% idle is per-CTA serial protocol latency
//      (TRYWAIT ~90 + bar ~47) at every chunk boundary. The wait for chunk
//      k+1 (whose data is already resident, lookahead 2) is moved into the
//      middle of chunk k's MMA stream where the 90 cyc overlap the HMMA
//      queue; only bar.sync remains exposed at the boundary.
//   CTA 128x128 @ occ 2, 8 warps (2x4), warp tile 64x32, bulk-copy ring.
//   M = 8192, K = 4096, N = 11008.
// ----------------------------------------------------------------------------

static constexpr int M_TOT = 8192;
static constexpr int K_TOT = 4096;
static constexpr int N_TOT = 11008;

static constexpr int BM = 128;
static constexpr int BN = 128;
static constexpr int KC = 64;                    // halves per chunk (128 B row)
static constexpr int NK = K_TOT / KC;            // 64
static constexpr int GRID_M = M_TOT / BM;        // 64
static constexpr int GRID_N = N_TOT / BN;        // 86
static constexpr int NCTAS = GRID_M * GRID_N;    // 5504
static constexpr int NSTAGE = 3;
static constexpr int TILE_BYTES = 16384;         // one (tile,kchunk) block
static constexpr int TILE_HALVES = 8192;
static constexpr int STAGE = 2 * TILE_BYTES;     // A + B = 32768
static constexpr int OFF_MBAR = NSTAGE * STAGE;  // 98304
static constexpr int SMEM_TOTAL = OFF_MBAR + 64; // 98368 -> 2 CTAs/SM

// Scratch (device globals — allocation-free per harness rules).
// Layout: block (tile, kc) at halves offset (tile*NK + kc)*8192; within a
// block: row r (0..127), col c (0..63 halves): r*64 + ((c16 ^ (r&7))*8) + c%8
__device__ __align__(128) __half g_Wt[(size_t)GRID_N * NK * TILE_HALVES];
__device__ __align__(128) __half g_Xt[(size_t)GRID_M * NK * TILE_HALVES];
__device__ float g_rowsum[M_TOT];                // sum_k fp16(x)

// ---------------------------------------------------------------- helpers ---
__device__ __forceinline__ uint32_t smem_u32(const void* p) {
    uint32_t a;
    asm("{ .reg .u64 t; cvta.to.shared.u64 t, %1; cvt.u32.u64 %0, t; }"
        : "=r"(a) : "l"(p));
    return a;
}

__device__ __forceinline__ uint32_t pack2(__half a, __half b) {
    return (uint32_t)__half_as_ushort(a) | ((uint32_t)__half_as_ushort(b) << 16);
}

__device__ __forceinline__ void mbar_init(uint32_t mbar, uint32_t cnt) {
    asm volatile("mbarrier.init.shared.b64 [%0], %1;" :: "r"(mbar), "r"(cnt)
                 : "memory");
}

__device__ __forceinline__ void mbar_expect_tx(uint32_t mbar, uint32_t bytes) {
    asm volatile("mbarrier.arrive.expect_tx.shared.b64 _, [%0], %1;"
                 :: "r"(mbar), "r"(bytes) : "memory");
}

__device__ __forceinline__ void bulk_cp(uint32_t dst, const void* src,
                                        uint32_t mbar) {
    asm volatile(
        "cp.async.bulk.shared::cluster.global.mbarrier::complete_tx::bytes "
        "[%0], [%1], %2, [%3];"
        :: "r"(dst), "l"(src), "r"((uint32_t)TILE_BYTES), "r"(mbar) : "memory");
}

__device__ __forceinline__ void mbar_wait(uint32_t mbar, uint32_t parity) {
    uint32_t done;
    asm volatile(
        "{\n\t.reg .pred p;\n\t"
        "mbarrier.try_wait.parity.acquire.cta.shared::cta.b64 p, [%1], %2;\n\t"
        "selp.b32 %0, 1, 0, p;\n\t}"
        : "=r"(done) : "r"(mbar), "r"(parity) : "memory");
    while (!done) {
        asm volatile(
            "{\n\t.reg .pred p;\n\t"
            "mbarrier.try_wait.parity.acquire.cta.shared::cta.b64 p, [%1], %2, 0x989680;\n\t"
            "selp.b32 %0, 1, 0, p;\n\t}"
            : "=r"(done) : "r"(mbar), "r"(parity) : "memory");
    }
}

#define LDSM4(r0, r1, r2, r3, addr)                                        \
    asm volatile("ldmatrix.sync.aligned.m8n8.x4.shared.b16 {%0,%1,%2,%3}, [%4];" \
                 : "=r"(r0), "=r"(r1), "=r"(r2), "=r"(r3) : "r"(addr))

#define MMA16816(C, A, B0, B1)                                             \
    asm volatile(                                                          \
        "mma.sync.aligned.m16n8k16.row.col.f32.f16.f16.f32 "               \
        "{%0,%1,%2,%3}, {%4,%5,%6,%7}, {%8,%9}, {%0,%1,%2,%3};"            \
        : "+f"((C)[0]), "+f"((C)[1]), "+f"((C)[2]), "+f"((C)[3])           \
        : "r"((A)[0]), "r"((A)[1]), "r"((A)[2]), "r"((A)[3]),              \
          "r"(B0), "r"(B1))

// one K=16 slice of the warp tile (4 ldsm A + 2 ldsm B + 16 MMA)
#define COMPUTE_KS(ks)                                                     \
    do {                                                                   \
        uint32_t af[4][4];                                                 \
        _Pragma("unroll")                                                  \
        for (int mt = 0; mt < 4; mt++) {                                   \
            uint32_t kc16 = (uint32_t)((ks) * 2) + akhi;                   \
            uint32_t ad = sa + arow128[mt] + ((kc16 ^ arow7[mt]) << 4);    \
            LDSM4(af[mt][0], af[mt][1], af[mt][2], af[mt][3], ad);         \
        }                                                                  \
        uint32_t bf[2][4];                                                 \
        _Pragma("unroll")                                                  \
        for (int p = 0; p < 2; p++) {                                      \
            uint32_t kc16 = (uint32_t)((ks) * 2) + bkhi;                   \
            uint32_t bd = sb + brow128[p] + ((kc16 ^ brow7[p]) << 4);      \
            LDSM4(bf[p][0], bf[p][1], bf[p][2], bf[p][3], bd);             \
        }                                                                  \
        _Pragma("unroll")                                                  \
        for (int mt = 0; mt < 4; mt++)                                     \
            _Pragma("unroll")                                              \
            for (int g = 0; g < 4; g++)                                    \
                MMA16816(acc[mt][g], af[mt], bf[g >> 1][(g & 1) * 2],      \
                         bf[g >> 1][(g & 1) * 2 + 1]);                     \
    } while (0)

// ------------------------------------------------------------- pre-passes ---
__global__ void dummy_shift() {}

// Merged prep. Blocks [0,8192): W -> g_Wt (tiled+swizzled, grid-stride).
// Blocks [8192,16384): one X row each -> g_Xt (tiled+swizzled) + rowsum.
__global__ void __launch_bounds__(256) prep_all(const float* __restrict__ x,
                                                const int* __restrict__ q) {
    const int tid = threadIdx.x;
    if (blockIdx.x < 8192) {
        const size_t total = (size_t)N_TOT * 1024;  // int4 groups (4 cols)
        const int4* q4 = (const int4*)q;
        for (size_t i = blockIdx.x * 256 + tid; i < total;
             i += (size_t)8192 * 256) {
            const int row = (int)(i >> 10);
            const int g = (int)(i & 1023);
            const int col0 = g * 4;
            const int nt = row >> 7, r128 = row & 127;
            const int kc = col0 >> 6;
            const int c16 = (col0 & 63) >> 3;
            const int inner = col0 & 7;  // 0 or 4 (halves)
            int4 v = q4[i];
            uint2 r;
            r.x = pack2(__int2half_rn(v.x), __int2half_rn(v.y));
            r.y = pack2(__int2half_rn(v.z), __int2half_rn(v.w));
            const size_t dst = ((size_t)(nt * NK + kc) << 13) + (r128 << 6) +
                               ((c16 ^ (r128 & 7)) << 3) + inner;
            *(uint2*)(g_Wt + dst) = r;
        }
    } else {
        const int row = blockIdx.x - 8192;
        const int mt = row >> 7, r128 = row & 127;
        const float4* xr = (const float4*)(x + (size_t)row * K_TOT) + tid * 4;
        float s = 0.f;
        uint32_t h[8];
#pragma unroll
        for (int i = 0; i < 4; i++) {
            float4 v = xr[i];
            __half h0 = __float2half_rn(v.x), h1 = __float2half_rn(v.y);
            __half h2 = __float2half_rn(v.z), h3 = __float2half_rn(v.w);
            s += __half2float(h0) + __half2float(h1) + __half2float(h2) +
                 __half2float(h3);
            h[i * 2 + 0] = pack2(h0, h1);
            h[i * 2 + 1] = pack2(h2, h3);
        }
        // cols [tid*16, tid*16+16): kc = tid/4, two 8-half groups
        const int kc = tid >> 2;
        const int c16a = (tid & 3) * 2;
        const size_t base = ((size_t)(mt * NK + kc) << 13) + (r128 << 6);
        const int sw = r128 & 7;
        *(uint4*)(g_Xt + base + ((c16a ^ sw) << 3)) =
            make_uint4(h[0], h[1], h[2], h[3]);
        *(uint4*)(g_Xt + base + (((c16a + 1) ^ sw) << 3)) =
            make_uint4(h[4], h[5], h[6], h[7]);

#pragma unroll
        for (int off = 16; off; off >>= 1) s += __shfl_xor_sync(0xFFFFFFFFu, s, off);
        __shared__ float red[8];
        if ((tid & 31) == 0) red[tid >> 5] = s;
        __syncthreads();
        if (tid == 0) {
            float t = 0.f;
#pragma unroll
            for (int j = 0; j < 8; j++) t += red[j];
            g_rowsum[row] = t;
        }
    }
}

// ------------------------------------------------------------ main kernel ---
__global__ void __launch_bounds__(256, 2)
gemm_f16(const float* __restrict__ scale, const float* __restrict__ zp,
         const float* __restrict__ bias, float* __restrict__ out) {
    extern __shared__ char smem[];
    const uint32_t sbase = smem_u32(smem);
    const uint32_t mb = sbase + OFF_MBAR;
    const int tid = threadIdx.x;
    const int lane = tid & 31;
    const int wid = tid >> 5;        // 0..7
    const int wr = wid & 1;          // warp row (M): 2 x 64
    const int wc = wid >> 1;         // warp col (N): 4 x 32

    // raster: groups of 8 M-tiles -> B slice of the group (~90MB) fits L2
    const int per = 8 * GRID_N;  // 688
    const int grp = blockIdx.x / per;
    const int rem = blockIdx.x % per;
    const int mtile = grp * 8 + (rem & 7);
    const int ntile = rem >> 3;
    const int m_base = mtile * BM;
    const int n_base = ntile * BN;

    if (tid == 0) {
#pragma unroll
        for (int j = 0; j < NSTAGE; j++) mbar_init(mb + j * 8, 1);
    }
    __syncthreads();

    const __half* srcA = g_Xt + ((size_t)mtile * NK << 13);
    const __half* srcB = g_Wt + ((size_t)ntile * NK << 13);

    // prologue: stages 0,1 <- chunks 0,1
    if (tid == 0) {
#pragma unroll
        for (int j = 0; j < 2; j++) {
            mbar_expect_tx(mb + j * 8, STAGE);
            bulk_cp(sbase + j * STAGE, srcA + ((size_t)j << 13), mb + j * 8);
            bulk_cp(sbase + j * STAGE + TILE_BYTES, srcB + ((size_t)j << 13),
                    mb + j * 8);
        }
    }

    float acc[4][4][4];
#pragma unroll
    for (int a = 0; a < 4; a++)
#pragma unroll
        for (int b = 0; b < 4; b++)
#pragma unroll
            for (int c = 0; c < 4; c++) acc[a][b][c] = 0.f;

    // ldmatrix address invariants
    uint32_t arow128[4], arow7[4];
#pragma unroll
    for (int mt = 0; mt < 4; mt++) {
        int r = wr * 64 + mt * 16 + (lane & 15);
        arow128[mt] = (uint32_t)r * 128u;
        arow7[mt] = (uint32_t)(r & 7);
    }
    const uint32_t akhi = (uint32_t)(lane >> 4);  // 0/1
    uint32_t brow128[2], brow7[2];
#pragma unroll
    for (int p = 0; p < 2; p++) {
        int r = wc * 32 + p * 16 + ((lane >> 4) & 1) * 8 + (lane & 7);
        brow128[p] = (uint32_t)r * 128u;
        brow7[p] = (uint32_t)(r & 7);
    }
    const uint32_t bkhi = (uint32_t)((lane >> 3) & 1);  // 0/1

    // wait for chunk 0 before entering the loop
    mbar_wait(mb + 0, 0);

    int s = 0;   uint32_t ph = 0;    // stage/parity of current chunk k
    int sn = 1;  uint32_t phn = 0;   // stage/parity of chunk k+1
#pragma unroll 1
    for (int k = 0; k < NK; k++) {
        const uint32_t sa = sbase + s * STAGE;
        const uint32_t sb = sa + TILE_BYTES;

        COMPUTE_KS(0);
        COMPUTE_KS(1);
        COMPUTE_KS(2);

        // hoisted wait: chunk k+1's stage was filled during k-1; the ~90cyc
        // TRYWAIT overlaps the outstanding HMMA queue from ks=0..2.
        if (k + 1 < NK) mbar_wait(mb + sn * 8, phn);

        COMPUTE_KS(3);

        __syncthreads();  // all warps done reading stage s (chunk k)

        if (tid == 0 && k + 2 < NK) {
            // refill the stage freed at iteration k-1's sync: (k+2)%3
            const int pf = s;  // (k+2)%3 == (k-1)%3 == s's predecessor cycle;
            // NOTE: with 3 stages, (k+2)%3 == (k-1)%3; s==k%3, so pf must be
            // computed from sn: pf = 3 - s - sn cyclic -> use sn's successor.
            const int pfr = (sn == 2) ? 0 : sn + 1;   // (k+2)%3
            (void)pf;
            mbar_expect_tx(mb + pfr * 8, STAGE);
            bulk_cp(sbase + pfr * STAGE, srcA + ((size_t)(k + 2) << 13),
                    mb + pfr * 8);
            bulk_cp(sbase + pfr * STAGE + TILE_BYTES,
                    srcB + ((size_t)(k + 2) << 13), mb + pfr * 8);
        }

        s = sn; ph = phn;
        sn = (sn == 2) ? 0 : sn + 1;
        if (sn == 0) phn ^= 1;
    }

    // ------------------------------------------------------------ epilogue --
    const float sc = __ldg(scale);
    const float msz = -sc * __ldg(zp);
    const int r0 = m_base + wr * 64 + (lane >> 2);
    float adj[4][2];
#pragma unroll
    for (int mt = 0; mt < 4; mt++)
#pragma unroll
        for (int h = 0; h < 2; h++)
            adj[mt][h] = msz * __ldg(&g_rowsum[r0 + mt * 16 + h * 8]);

#pragma unroll
    for (int mt = 0; mt < 4; mt++) {
        const int r = r0 + mt * 16;
#pragma unroll
        for (int g = 0; g < 4; g++) {
            const int c = n_base + wc * 32 + g * 8 + (lane & 3) * 2;
            const float2 bv = *(const float2*)(bias + c);
            float2 v0, v1;
            v0.x = fmaf(sc, acc[mt][g][0], adj[mt][0] + bv.x);
            v0.y = fmaf(sc, acc[mt][g][1], adj[mt][0] + bv.y);
            v1.x = fmaf(sc, acc[mt][g][2], adj[mt][1] + bv.x);
            v1.y = fmaf(sc, acc[mt][g][3], adj[mt][1] + bv.y);
            *(float2*)(out + (size_t)r * N_TOT + c) = v0;
            *(float2*)(out + (size_t)(r + 8) * N_TOT + c) = v1;
        }
    }
}

// ---------------------------------------------------------------- launch ----
extern "C" void kernel_launch(void* const* d_in, const int* in_sizes, int n_in,
                              void* d_out, int out_size) {
    (void)in_sizes; (void)n_in; (void)out_size;
    const float* x     = (const float*)d_in[0];
    const int*   wq    = (const int*)d_in[1];
    const float* scale = (const float*)d_in[2];
    const float* zp    = (const float*)d_in[3];
    const float* bias  = (const float*)d_in[4];
    float* out = (float*)d_out;

    dummy_shift<<<1, 32>>>();   // 2 dummies: 4 launches/replay -> ncu hits GEMM
    dummy_shift<<<1, 32>>>();
    prep_all<<<16384, 256>>>(x, wq);

    cudaFuncSetAttribute(gemm_f16, cudaFuncAttributeMaxDynamicSharedMemorySize,
                         SMEM_TOTAL);
    gemm_f16<<<NCTAS, 256, SMEM_TOTAL>>>(scale, zp, bias, out);
}

// round 16
// speedup vs baseline: 1.0621x; 1.0621x over previous
#include <cuda_runtime.h>
#include <cuda_fp16.h>
#include <cstdint>

// ----------------------------------------------------------------------------
// Linear4bit via fp16 mma.sync (tcgen05 unavailable: PTX target sm_103).
//   out[m,o] = scale*(sum_k x_h[m,k]*wq[o,k]) - scale*zp*rowsum_h[m] + bias[o]
// R16 (FINAL): R8 configuration — the measured optimum after 15 rounds.
//   - wq in {0..15} exact in fp16; only rounding is x->fp16 (+rowsum fixup)
//   - prep pass writes pre-swizzled, tile-major fp16 scratch; GEMM stages are
//     filled by cp.async.bulk (2 copies/chunk) into an mbarrier ring
//   - CTA 128x128 @ occupancy 2, 8 warps (2x4), warp tile 64x32, 3 stages
//   - boundary protocol: per-chunk mbar_wait + bar.sync (5 alternative
//     schemes measured slower or deadlocked; tensor pipe = 87.4%, HMMA rt=8)
//   M = 8192, K = 4096, N = 11008.
// ----------------------------------------------------------------------------

static constexpr int M_TOT = 8192;
static constexpr int K_TOT = 4096;
static constexpr int N_TOT = 11008;

static constexpr int BM = 128;
static constexpr int BN = 128;
static constexpr int KC = 64;                    // halves per chunk (128 B row)
static constexpr int NK = K_TOT / KC;            // 64
static constexpr int GRID_M = M_TOT / BM;        // 64
static constexpr int GRID_N = N_TOT / BN;        // 86
static constexpr int NCTAS = GRID_M * GRID_N;    // 5504
static constexpr int NSTAGE = 3;
static constexpr int TILE_BYTES = 16384;         // one (tile,kchunk) block
static constexpr int TILE_HALVES = 8192;
static constexpr int STAGE = 2 * TILE_BYTES;     // A + B = 32768
static constexpr int OFF_MBAR = NSTAGE * STAGE;  // 98304
static constexpr int SMEM_TOTAL = OFF_MBAR + 64; // 98368 -> 2 CTAs/SM

// Scratch (device globals — allocation-free per harness rules).
// Layout: block (tile, kc) at halves offset (tile*NK + kc)*8192; within a
// block: row r (0..127), col c (0..63 halves): r*64 + ((c16 ^ (r&7))*8) + c%8
__device__ __align__(128) __half g_Wt[(size_t)GRID_N * NK * TILE_HALVES];
__device__ __align__(128) __half g_Xt[(size_t)GRID_M * NK * TILE_HALVES];
__device__ float g_rowsum[M_TOT];                // sum_k fp16(x)

// ---------------------------------------------------------------- helpers ---
__device__ __forceinline__ uint32_t smem_u32(const void* p) {
    uint32_t a;
    asm("{ .reg .u64 t; cvta.to.shared.u64 t, %1; cvt.u32.u64 %0, t; }"
        : "=r"(a) : "l"(p));
    return a;
}

__device__ __forceinline__ uint32_t pack2(__half a, __half b) {
    return (uint32_t)__half_as_ushort(a) | ((uint32_t)__half_as_ushort(b) << 16);
}

__device__ __forceinline__ void mbar_init(uint32_t mbar, uint32_t cnt) {
    asm volatile("mbarrier.init.shared.b64 [%0], %1;" :: "r"(mbar), "r"(cnt)
                 : "memory");
}

__device__ __forceinline__ void mbar_expect_tx(uint32_t mbar, uint32_t bytes) {
    asm volatile("mbarrier.arrive.expect_tx.shared.b64 _, [%0], %1;"
                 :: "r"(mbar), "r"(bytes) : "memory");
}

__device__ __forceinline__ void bulk_cp(uint32_t dst, const void* src,
                                        uint32_t mbar) {
    asm volatile(
        "cp.async.bulk.shared::cluster.global.mbarrier::complete_tx::bytes "
        "[%0], [%1], %2, [%3];"
        :: "r"(dst), "l"(src), "r"((uint32_t)TILE_BYTES), "r"(mbar) : "memory");
}

__device__ __forceinline__ void mbar_wait(uint32_t mbar, uint32_t parity) {
    uint32_t done;
    asm volatile(
        "{\n\t.reg .pred p;\n\t"
        "mbarrier.try_wait.parity.acquire.cta.shared::cta.b64 p, [%1], %2;\n\t"
        "selp.b32 %0, 1, 0, p;\n\t}"
        : "=r"(done) : "r"(mbar), "r"(parity) : "memory");
    while (!done) {
        asm volatile(
            "{\n\t.reg .pred p;\n\t"
            "mbarrier.try_wait.parity.acquire.cta.shared::cta.b64 p, [%1], %2, 0x989680;\n\t"
            "selp.b32 %0, 1, 0, p;\n\t}"
            : "=r"(done) : "r"(mbar), "r"(parity) : "memory");
    }
}

#define LDSM4(r0, r1, r2, r3, addr)                                        \
    asm volatile("ldmatrix.sync.aligned.m8n8.x4.shared.b16 {%0,%1,%2,%3}, [%4];" \
                 : "=r"(r0), "=r"(r1), "=r"(r2), "=r"(r3) : "r"(addr))

#define MMA16816(C, A, B0, B1)                                             \
    asm volatile(                                                          \
        "mma.sync.aligned.m16n8k16.row.col.f32.f16.f16.f32 "               \
        "{%0,%1,%2,%3}, {%4,%5,%6,%7}, {%8,%9}, {%0,%1,%2,%3};"            \
        : "+f"((C)[0]), "+f"((C)[1]), "+f"((C)[2]), "+f"((C)[3])           \
        : "r"((A)[0]), "r"((A)[1]), "r"((A)[2]), "r"((A)[3]),              \
          "r"(B0), "r"(B1))

// ------------------------------------------------------------- pre-passes ---
// Merged prep. Blocks [0,8192): W -> g_Wt (tiled+swizzled, grid-stride).
// Blocks [8192,16384): one X row each -> g_Xt (tiled+swizzled) + rowsum.
__global__ void __launch_bounds__(256) prep_all(const float* __restrict__ x,
                                                const int* __restrict__ q) {
    const int tid = threadIdx.x;
    if (blockIdx.x < 8192) {
        const size_t total = (size_t)N_TOT * 1024;  // int4 groups (4 cols)
        const int4* q4 = (const int4*)q;
        for (size_t i = blockIdx.x * 256 + tid; i < total;
             i += (size_t)8192 * 256) {
            const int row = (int)(i >> 10);
            const int g = (int)(i & 1023);
            const int col0 = g * 4;
            const int nt = row >> 7, r128 = row & 127;
            const int kc = col0 >> 6;
            const int c16 = (col0 & 63) >> 3;
            const int inner = col0 & 7;  // 0 or 4 (halves)
            int4 v = q4[i];
            uint2 r;
            r.x = pack2(__int2half_rn(v.x), __int2half_rn(v.y));
            r.y = pack2(__int2half_rn(v.z), __int2half_rn(v.w));
            const size_t dst = ((size_t)(nt * NK + kc) << 13) + (r128 << 6) +
                               ((c16 ^ (r128 & 7)) << 3) + inner;
            *(uint2*)(g_Wt + dst) = r;
        }
    } else {
        const int row = blockIdx.x - 8192;
        const int mt = row >> 7, r128 = row & 127;
        const float4* xr = (const float4*)(x + (size_t)row * K_TOT) + tid * 4;
        float s = 0.f;
        uint32_t h[8];
#pragma unroll
        for (int i = 0; i < 4; i++) {
            float4 v = xr[i];
            __half h0 = __float2half_rn(v.x), h1 = __float2half_rn(v.y);
            __half h2 = __float2half_rn(v.z), h3 = __float2half_rn(v.w);
            s += __half2float(h0) + __half2float(h1) + __half2float(h2) +
                 __half2float(h3);
            h[i * 2 + 0] = pack2(h0, h1);
            h[i * 2 + 1] = pack2(h2, h3);
        }
        // cols [tid*16, tid*16+16): kc = tid/4, two 8-half groups
        const int kc = tid >> 2;
        const int c16a = (tid & 3) * 2;
        const size_t base = ((size_t)(mt * NK + kc) << 13) + (r128 << 6);
        const int sw = r128 & 7;
        *(uint4*)(g_Xt + base + ((c16a ^ sw) << 3)) =
            make_uint4(h[0], h[1], h[2], h[3]);
        *(uint4*)(g_Xt + base + (((c16a + 1) ^ sw) << 3)) =
            make_uint4(h[4], h[5], h[6], h[7]);

#pragma unroll
        for (int off = 16; off; off >>= 1) s += __shfl_xor_sync(0xFFFFFFFFu, s, off);
        __shared__ float red[8];
        if ((tid & 31) == 0) red[tid >> 5] = s;
        __syncthreads();
        if (tid == 0) {
            float t = 0.f;
#pragma unroll
            for (int j = 0; j < 8; j++) t += red[j];
            g_rowsum[row] = t;
        }
    }
}

// ------------------------------------------------------------ main kernel ---
__global__ void __launch_bounds__(256, 2)
gemm_f16(const float* __restrict__ scale, const float* __restrict__ zp,
         const float* __restrict__ bias, float* __restrict__ out) {
    extern __shared__ char smem[];
    const uint32_t sbase = smem_u32(smem);
    const uint32_t mb = sbase + OFF_MBAR;
    const int tid = threadIdx.x;
    const int lane = tid & 31;
    const int wid = tid >> 5;        // 0..7
    const int wr = wid & 1;          // warp row (M): 2 x 64
    const int wc = wid >> 1;         // warp col (N): 4 x 32

    // raster: groups of 8 M-tiles -> B slice of the group (~90MB) fits L2
    const int per = 8 * GRID_N;  // 688
    const int grp = blockIdx.x / per;
    const int rem = blockIdx.x % per;
    const int mtile = grp * 8 + (rem & 7);
    const int ntile = rem >> 3;
    const int m_base = mtile * BM;
    const int n_base = ntile * BN;

    if (tid == 0) {
#pragma unroll
        for (int j = 0; j < NSTAGE; j++) mbar_init(mb + j * 8, 1);
    }
    __syncthreads();

    const __half* srcA = g_Xt + ((size_t)mtile * NK << 13);
    const __half* srcB = g_Wt + ((size_t)ntile * NK << 13);

    // prologue: stages 0,1 <- chunks 0,1
    if (tid == 0) {
#pragma unroll
        for (int j = 0; j < 2; j++) {
            mbar_expect_tx(mb + j * 8, STAGE);
            bulk_cp(sbase + j * STAGE, srcA + ((size_t)j << 13), mb + j * 8);
            bulk_cp(sbase + j * STAGE + TILE_BYTES, srcB + ((size_t)j << 13),
                    mb + j * 8);
        }
    }

    float acc[4][4][4];
#pragma unroll
    for (int a = 0; a < 4; a++)
#pragma unroll
        for (int b = 0; b < 4; b++)
#pragma unroll
            for (int c = 0; c < 4; c++) acc[a][b][c] = 0.f;

    // ldmatrix address invariants
    uint32_t arow128[4], arow7[4];
#pragma unroll
    for (int mt = 0; mt < 4; mt++) {
        int r = wr * 64 + mt * 16 + (lane & 15);
        arow128[mt] = (uint32_t)r * 128u;
        arow7[mt] = (uint32_t)(r & 7);
    }
    const uint32_t akhi = (uint32_t)(lane >> 4);  // 0/1
    uint32_t brow128[2], brow7[2];
#pragma unroll
    for (int p = 0; p < 2; p++) {
        int r = wc * 32 + p * 16 + ((lane >> 4) & 1) * 8 + (lane & 7);
        brow128[p] = (uint32_t)r * 128u;
        brow7[p] = (uint32_t)(r & 7);
    }
    const uint32_t bkhi = (uint32_t)((lane >> 3) & 1);  // 0/1

    int s = 0;   // stage of chunk k
    int pf = 2;  // stage receiving chunk k+2
    uint32_t ph = 0;
#pragma unroll 1
    for (int k = 0; k < NK; k++) {
        mbar_wait(mb + s * 8, ph);
        __syncthreads();  // all warps done reading stage pf (chunk k-1)

        if (tid == 0) {
            const int kn = k + 2;
            if (kn < NK) {
                mbar_expect_tx(mb + pf * 8, STAGE);
                bulk_cp(sbase + pf * STAGE, srcA + ((size_t)kn << 13),
                        mb + pf * 8);
                bulk_cp(sbase + pf * STAGE + TILE_BYTES,
                        srcB + ((size_t)kn << 13), mb + pf * 8);
            }
        }

        const uint32_t sa = sbase + s * STAGE;
        const uint32_t sb = sa + TILE_BYTES;
#pragma unroll
        for (int ks = 0; ks < 4; ks++) {
            uint32_t af[4][4];
#pragma unroll
            for (int mt = 0; mt < 4; mt++) {
                uint32_t kc16 = (uint32_t)(ks * 2) + akhi;
                uint32_t ad = sa + arow128[mt] + ((kc16 ^ arow7[mt]) << 4);
                LDSM4(af[mt][0], af[mt][1], af[mt][2], af[mt][3], ad);
            }
            uint32_t bf[2][4];
#pragma unroll
            for (int p = 0; p < 2; p++) {
                uint32_t kc16 = (uint32_t)(ks * 2) + bkhi;
                uint32_t bd = sb + brow128[p] + ((kc16 ^ brow7[p]) << 4);
                LDSM4(bf[p][0], bf[p][1], bf[p][2], bf[p][3], bd);
            }
#pragma unroll
            for (int mt = 0; mt < 4; mt++)
#pragma unroll
                for (int g = 0; g < 4; g++)
                    MMA16816(acc[mt][g], af[mt], bf[g >> 1][(g & 1) * 2],
                             bf[g >> 1][(g & 1) * 2 + 1]);
        }

        pf = s;                       // stage s is free after this chunk
        s = (s == 2) ? 0 : s + 1;
        if (s == 0) ph ^= 1;
    }

    // ------------------------------------------------------------ epilogue --
    const float sc = __ldg(scale);
    const float msz = -sc * __ldg(zp);
    const int r0 = m_base + wr * 64 + (lane >> 2);
    float adj[4][2];
#pragma unroll
    for (int mt = 0; mt < 4; mt++)
#pragma unroll
        for (int h = 0; h < 2; h++)
            adj[mt][h] = msz * __ldg(&g_rowsum[r0 + mt * 16 + h * 8]);

#pragma unroll
    for (int mt = 0; mt < 4; mt++) {
        const int r = r0 + mt * 16;
#pragma unroll
        for (int g = 0; g < 4; g++) {
            const int c = n_base + wc * 32 + g * 8 + (lane & 3) * 2;
            const float2 bv = *(const float2*)(bias + c);
            float2 v0, v1;
            v0.x = fmaf(sc, acc[mt][g][0], adj[mt][0] + bv.x);
            v0.y = fmaf(sc, acc[mt][g][1], adj[mt][0] + bv.y);
            v1.x = fmaf(sc, acc[mt][g][2], adj[mt][1] + bv.x);
            v1.y = fmaf(sc, acc[mt][g][3], adj[mt][1] + bv.y);
            *(float2*)(out + (size_t)r * N_TOT + c) = v0;
            *(float2*)(out + (size_t)(r + 8) * N_TOT + c) = v1;
        }
    }
}

// ---------------------------------------------------------------- launch ----
extern "C" void kernel_launch(void* const* d_in, const int* in_sizes, int n_in,
                              void* d_out, int out_size) {
    (void)in_sizes; (void)n_in; (void)out_size;
    const float* x     = (const float*)d_in[0];
    const int*   wq    = (const int*)d_in[1];
    const float* scale = (const float*)d_in[2];
    const float* zp    = (const float*)d_in[3];
    const float* bias  = (const float*)d_in[4];
    float* out = (float*)d_out;

    prep_all<<<16384, 256>>>(x, wq);

    cudaFuncSetAttribute(gemm_f16, cudaFuncAttributeMaxDynamicSharedMemorySize,
                         SMEM_TOTAL);
    gemm_f16<<<NCTAS, 256, SMEM_TOTAL>>>(scale, zp, bias, out);
}